// round 15
// baseline (speedup 1.0000x reference)
#include <cuda_runtime.h>
#include <cuda_fp16.h>
#include <cstdint>
#include <cstddef>

#define NROWS 8192
#define CDIM  128

// ---------------- device scratch ----------------
__device__ float  g_dinv[NROWS];
__device__ __half g_yT_h[CDIM * NROWS];          // yT[c][j] = (xW^T)_{j,c} fp16 (unscaled)
__device__ float  g_y[NROWS * CDIM];             // y[j][c] fp32 (unscaled)
__device__ float  g_part[4 * NROWS * CDIM];      // split-K partials
__device__ int    g_cnt[64];                     // per-tile arrival counters (self-resetting)

// ---------------- helpers ----------------
__device__ __forceinline__ uint32_t smem_u32(const void* p) {
    uint32_t a;
    asm("{ .reg .u64 t; cvta.to.shared.u64 t, %1; cvt.u32.u64 %0, t; }" : "=r"(a) : "l"(p));
    return a;
}
__device__ __forceinline__ uint32_t pack_f16x2(float x, float y) {
    uint32_t h;
    asm("cvt.rn.f16x2.f32 %0, %1, %2;" : "=r"(h) : "f"(y), "f"(x));
    return h;
}
#define CP_ASYNC16(dst, src) \
    asm volatile("cp.async.cg.shared.global [%0], [%1], 16;" :: "r"(dst), "l"(src) : "memory")
#define CP_COMMIT() asm volatile("cp.async.commit_group;" ::: "memory")
#define CP_WAIT0()  asm volatile("cp.async.wait_group 0;" ::: "memory")

#define LDMATRIX_X4(r0, r1, r2, r3, addr)                                    \
    asm volatile("ldmatrix.sync.aligned.m8n8.x4.shared.b16 {%0,%1,%2,%3}, [%4];" \
                 : "=r"(r0), "=r"(r1), "=r"(r2), "=r"(r3) : "r"(addr))

__device__ __forceinline__ void mma_f16(float& d0, float& d1, float& d2, float& d3,
                                        uint32_t a0, uint32_t a1, uint32_t a2, uint32_t a3,
                                        uint32_t b0, uint32_t b1) {
    asm volatile(
        "mma.sync.aligned.m16n8k16.row.col.f32.f16.f16.f32 "
        "{%0,%1,%2,%3}, {%4,%5,%6,%7}, {%8,%9}, {%0,%1,%2,%3};"
        : "+f"(d0), "+f"(d1), "+f"(d2), "+f"(d3)
        : "r"(a0), "r"(a1), "r"(a2), "r"(a3), "r"(b0), "r"(b1));
}

// ============================================================================
// K1 (per 4096-row chunk): dinv[i] = rsqrt(1 + rowsum)
// ============================================================================
__global__ void __launch_bounds__(256) k1_rowsum(const float* __restrict__ adj, int chunk) {
    const int row = chunk * 4096 + blockIdx.x;
    const float4* p = reinterpret_cast<const float4*>(adj + (size_t)row * NROWS);
    float s = 0.0f;
    #pragma unroll 4
    for (int i = threadIdx.x; i < NROWS / 4; i += 256) {
        float4 v = p[i];
        s += (v.x + v.y) + (v.z + v.w);
    }
    #pragma unroll
    for (int o = 16; o > 0; o >>= 1) s += __shfl_xor_sync(0xFFFFFFFFu, s, o);
    __shared__ float ws[8];
    if ((threadIdx.x & 31) == 0) ws[threadIdx.x >> 5] = s;
    __syncthreads();
    if (threadIdx.x == 0) {
        float t = 0.0f;
        #pragma unroll
        for (int i = 0; i < 8; i++) t += ws[i];
        g_dinv[row] = rsqrtf(t + 1.0f);
    }
}

// ============================================================================
// K2a: y = x@W^T (unscaled) fp32 + fp16-transposed. Launched FIRST.
// ============================================================================
__global__ void __launch_bounds__(128) k2a_y(const float* __restrict__ x,
                                             const float* __restrict__ W) {
    extern __shared__ float sh2[];
    float* Ws = sh2;                 // [128][132]
    float* xs = sh2 + 128 * 132;     // [16][128]
    const int c = threadIdx.x;
    const int j0 = blockIdx.x * 16;

    for (int idx = c; idx < 128 * 128; idx += 128)
        Ws[(idx >> 7) * 132 + (idx & 127)] = W[idx];
    for (int idx = c; idx < 16 * 128; idx += 128)
        xs[idx] = x[(size_t)(j0 + (idx >> 7)) * 128 + (idx & 127)];
    __syncthreads();

    float acc[16];
    #pragma unroll
    for (int r = 0; r < 16; r++) acc[r] = 0.0f;
    for (int k = 0; k < 128; k += 4) {
        float4 wv = *reinterpret_cast<const float4*>(&Ws[c * 132 + k]);
        #pragma unroll
        for (int r = 0; r < 16; r++) {
            float4 xv = *reinterpret_cast<const float4*>(&xs[r * 128 + k]);
            acc[r] += xv.x * wv.x + xv.y * wv.y + xv.z * wv.z + xv.w * wv.w;
        }
    }
    #pragma unroll
    for (int r = 0; r < 16; r++)
        g_y[(size_t)(j0 + r) * 128 + c] = acc[r];
    #pragma unroll
    for (int m = 0; m < 2; m++) {
        uint4 q;
        q.x = pack_f16x2(acc[8*m+0], acc[8*m+1]);
        q.y = pack_f16x2(acc[8*m+2], acc[8*m+3]);
        q.z = pack_f16x2(acc[8*m+4], acc[8*m+5]);
        q.w = pack_f16x2(acc[8*m+6], acc[8*m+7]);
        *reinterpret_cast<uint4*>(&g_yT_h[(size_t)c * NROWS + j0 + 8 * m]) = q;
    }
}

// ============================================================================
// K3 (two launches of 128 CTAs): slices {ks_base, ks_base+1}.
// R14 GEMM body (dinv folded into A) + last-arriver fused epilogue.
// ============================================================================
static constexpr int BK = 32;
static constexpr int RSTRIDE = 80;
static constexpr int TILE_B = 128 * RSTRIDE;
static constexpr int SMEM_K3 = 4 * TILE_B;         // 40960

__global__ void __launch_bounds__(256, 2) k3_gemm(const float* __restrict__ adj,
                                                  const float* __restrict__ bias,
                                                  float* __restrict__ out,
                                                  int ks_base) {
    extern __shared__ char sm3[];
    const uint32_t base = smem_u32(sm3);
    const int tid = threadIdx.x;
    const int wid = tid >> 5, lane = tid & 31;
    const int gid = lane >> 2, tig = lane & 3;
    const int wm = wid & 3;
    const int wn = wid >> 2;

    const int tile = blockIdx.x & 63;
    const int ks = ks_base + (blockIdx.x >> 6);
    const int m0 = tile * 128;
    const int kbase = ks * 2048;
    const int NK = 2048 / BK;        // 64

    const uint32_t Ab0 = base, Ab1 = base + TILE_B;
    const uint32_t Bb0 = base + 2 * TILE_B, Bb1 = base + 3 * TILE_B;

    const int ar[4] = { (tid + 0) >> 3, (tid + 256) >> 3, (tid + 512) >> 3, (tid + 768) >> 3 };
    const int aqf = tid & 7;

    float4 pf[4];
    float4 dv;
    #define LDA(kt) do {                                                         \
        const int _k0 = kbase + (kt) * BK;                                       \
        dv = *reinterpret_cast<const float4*>(g_dinv + _k0 + aqf * 4);           \
        _Pragma("unroll")                                                        \
        for (int i = 0; i < 4; i++)                                              \
            pf[i] = *reinterpret_cast<const float4*>(                            \
                adj + (size_t)(m0 + ar[i]) * NROWS + _k0 + aqf * 4);             \
    } while (0)

    #define STA(buf) do {                                                        \
        _Pragma("unroll")                                                        \
        for (int i = 0; i < 4; i++) {                                            \
            uint32_t h0 = pack_f16x2(pf[i].x * dv.x, pf[i].y * dv.y);            \
            uint32_t h1 = pack_f16x2(pf[i].z * dv.z, pf[i].w * dv.w);            \
            asm volatile("st.shared.v2.b32 [%0], {%1,%2};"                       \
                :: "r"((buf) + ar[i] * RSTRIDE + aqf * 8), "r"(h0), "r"(h1)      \
                : "memory");                                                     \
        }                                                                        \
    } while (0)

    #define CPB(kt, buf) do {                                                    \
        const int _k0 = kbase + (kt) * BK;                                       \
        _Pragma("unroll")                                                        \
        for (int i = 0; i < 2; i++) {                                            \
            const int id = tid + 256 * i;                                        \
            const int r = id >> 2, q = id & 3;                                   \
            CP_ASYNC16((buf) + r * RSTRIDE + q * 16,                             \
                       (const void*)(g_yT_h + (size_t)r * NROWS + _k0 + q * 8)); \
        }                                                                        \
    } while (0)

    float acc[2][8][4];
    #pragma unroll
    for (int i = 0; i < 2; i++)
        #pragma unroll
        for (int j = 0; j < 8; j++)
            #pragma unroll
            for (int t = 0; t < 4; t++) acc[i][j][t] = 0.0f;

    LDA(0);
    CPB(0, Bb0); CP_COMMIT();

    for (int kt = 0; kt < NK; kt++) {
        const uint32_t Ab = (kt & 1) ? Ab1 : Ab0;
        const uint32_t Bb = (kt & 1) ? Bb1 : Bb0;
        STA(Ab);
        CP_WAIT0();
        __syncthreads();
        if (kt + 1 < NK) {
            LDA(kt + 1);
            CPB(kt + 1, (kt & 1) ? Bb0 : Bb1);
            CP_COMMIT();
        }
        #pragma unroll
        for (int s = 0; s < 2; s++) {
            const int ch = 2 * s + (lane >> 4);
            uint32_t a[2][4], b[4][4];
            #pragma unroll
            for (int mt = 0; mt < 2; mt++) {
                const int r = wm * 32 + mt * 16 + (lane & 15);
                LDMATRIX_X4(a[mt][0], a[mt][1], a[mt][2], a[mt][3],
                            Ab + r * RSTRIDE + ch * 16);
            }
            #pragma unroll
            for (int p = 0; p < 4; p++) {
                const int r = wn * 64 + p * 16 + (lane & 15);
                LDMATRIX_X4(b[p][0], b[p][1], b[p][2], b[p][3],
                            Bb + r * RSTRIDE + ch * 16);
            }
            #pragma unroll
            for (int mt = 0; mt < 2; mt++)
                #pragma unroll
                for (int nt = 0; nt < 8; nt++) {
                    const int p = nt >> 1, sel = nt & 1;
                    mma_f16(acc[mt][nt][0], acc[mt][nt][1], acc[mt][nt][2], acc[mt][nt][3],
                            a[mt][0], a[mt][1], a[mt][2], a[mt][3],
                            b[p][sel], b[p][2 + sel]);
                }
        }
        __syncthreads();
    }

    // ---- write this slice's partial ----
    float* part = g_part + (size_t)ks * (NROWS * CDIM) + (size_t)m0 * CDIM;
    #pragma unroll
    for (int mt = 0; mt < 2; mt++) {
        const int r0 = wm * 32 + mt * 16 + gid;
        #pragma unroll
        for (int nt = 0; nt < 8; nt++) {
            const int col = wn * 64 + nt * 8 + tig * 2;
            *reinterpret_cast<float2*>(part + (size_t)r0 * 128 + col) =
                make_float2(acc[mt][nt][0], acc[mt][nt][1]);
            *reinterpret_cast<float2*>(part + (size_t)(r0 + 8) * 128 + col) =
                make_float2(acc[mt][nt][2], acc[mt][nt][3]);
        }
    }
    #undef LDA
    #undef STA
    #undef CPB

    // ---- last-arriver fused epilogue (non-blocking, deterministic) ----
    __threadfence();
    __syncthreads();
    __shared__ int s_last;
    if (tid == 0) {
        const int old = atomicAdd(&g_cnt[tile], 1);
        s_last = (old == 3);
        if (old == 3) g_cnt[tile] = 0;   // self-reset for next replay
    }
    __syncthreads();
    if (s_last) {
        __threadfence();
        const size_t tbase = (size_t)m0 * CDIM;
        for (int e = tid; e < 128 * CDIM / 4; e += 256) {
            const int r = e >> 5;
            const int c4 = (e & 31) * 4;
            const size_t off = tbase + (size_t)r * CDIM + c4;
            float4 sum = *reinterpret_cast<const float4*>(g_part + off);
            #pragma unroll
            for (int sp = 1; sp < 4; sp++) {
                const float4 p = *reinterpret_cast<const float4*>(
                    g_part + (size_t)sp * (NROWS * CDIM) + off);
                sum.x += p.x; sum.y += p.y; sum.z += p.z; sum.w += p.w;
            }
            const float di = g_dinv[m0 + r];
            const float d2 = di * di;
            const float4 y4 = *reinterpret_cast<const float4*>(g_y + off);
            const float4 bb = *reinterpret_cast<const float4*>(bias + c4);
            float4 o;
            o.x = di * sum.x + d2 * y4.x + bb.x;
            o.y = di * sum.y + d2 * y4.y + bb.y;
            o.z = di * sum.z + d2 * y4.z + bb.z;
            o.w = di * sum.w + d2 * y4.w + bb.w;
            *reinterpret_cast<float4*>(out + off) = o;
        }
    }
}

// ============================================================================
// host: events-only pipelining (no device-side gating)
// ============================================================================
static cudaStream_t g_stA, g_stB;
static cudaEvent_t  g_evY, g_evC0, g_evC1, g_evGA, g_evGB;
namespace {
struct HandleInit {
    HandleInit() {
        cudaStreamCreateWithFlags(&g_stA, cudaStreamNonBlocking);
        cudaStreamCreateWithFlags(&g_stB, cudaStreamNonBlocking);
        cudaEventCreateWithFlags(&g_evY, cudaEventDisableTiming);
        cudaEventCreateWithFlags(&g_evC0, cudaEventDisableTiming);
        cudaEventCreateWithFlags(&g_evC1, cudaEventDisableTiming);
        cudaEventCreateWithFlags(&g_evGA, cudaEventDisableTiming);
        cudaEventCreateWithFlags(&g_evGB, cudaEventDisableTiming);
    }
} g_handle_init;
}

extern "C" void kernel_launch(void* const* d_in, const int* in_sizes, int n_in,
                              void* d_out, int out_size) {
    (void)in_sizes; (void)n_in; (void)out_size;
    const float* x   = (const float*)d_in[0];
    const float* adj = (const float*)d_in[1];
    const float* W   = (const float*)d_in[2];
    const float* b   = (const float*)d_in[3];
    float* out = (float*)d_out;

    const int smem_k2 = (128 * 132 + 16 * 128) * 4;
    cudaFuncSetAttribute(k2a_y, cudaFuncAttributeMaxDynamicSharedMemorySize, smem_k2);
    cudaFuncSetAttribute(k3_gemm, cudaFuncAttributeMaxDynamicSharedMemorySize, SMEM_K3);

    // stream 0: k2a FIRST (drains in ~6us before the k1 flood), then k1 chunks
    k2a_y<<<NROWS / 16, 128, smem_k2>>>(x, W);
    cudaEventRecord(g_evY, 0);
    k1_rowsum<<<4096, 256>>>(adj, 0);
    cudaEventRecord(g_evC0, 0);
    k1_rowsum<<<4096, 256>>>(adj, 1);
    cudaEventRecord(g_evC1, 0);

    // k3a: slices 0,1 (needs dinv rows 0..4095 + y)
    cudaStreamWaitEvent(g_stA, g_evY, 0);
    cudaStreamWaitEvent(g_stA, g_evC0, 0);
    k3_gemm<<<128, 256, SMEM_K3, g_stA>>>(adj, b, out, 0);
    cudaEventRecord(g_evGA, g_stA);

    // k3b: slices 2,3 (needs dinv rows 4096..8191 + y)
    cudaStreamWaitEvent(g_stB, g_evY, 0);
    cudaStreamWaitEvent(g_stB, g_evC1, 0);
    k3_gemm<<<128, 256, SMEM_K3, g_stB>>>(adj, b, out, 2);
    cudaEventRecord(g_evGB, g_stB);

    // join on stream 0 so the harness's downstream work is ordered correctly
    cudaStreamWaitEvent(0, g_evGA, 0);
    cudaStreamWaitEvent(0, g_evGB, 0);
}

// round 16
// speedup vs baseline: 1.0220x; 1.0220x over previous
#include <cuda_runtime.h>
#include <cuda_fp16.h>
#include <cstdint>
#include <cstddef>

#define NROWS 8192
#define CDIM  128

// ---------------- device scratch ----------------
__device__ float  g_dinv[NROWS];
__device__ __half g_yT_h[CDIM * NROWS];          // yT[c][j] = (xW^T)_{j,c} fp16 (unscaled)
__device__ float  g_y[NROWS * CDIM];             // y[j][c] fp32 (unscaled)
__device__ float  g_part[4 * NROWS * CDIM];      // split-K partials
__device__ int    g_cnt[64];                     // per-tile arrival counters (self-resetting)

// ---------------- helpers ----------------
__device__ __forceinline__ uint32_t smem_u32(const void* p) {
    uint32_t a;
    asm("{ .reg .u64 t; cvta.to.shared.u64 t, %1; cvt.u32.u64 %0, t; }" : "=r"(a) : "l"(p));
    return a;
}
__device__ __forceinline__ uint32_t pack_f16x2(float x, float y) {
    uint32_t h;
    asm("cvt.rn.f16x2.f32 %0, %1, %2;" : "=r"(h) : "f"(y), "f"(x));
    return h;
}
#define CP_ASYNC16(dst, src) \
    asm volatile("cp.async.cg.shared.global [%0], [%1], 16;" :: "r"(dst), "l"(src) : "memory")
#define CP_COMMIT() asm volatile("cp.async.commit_group;" ::: "memory")
#define CP_WAIT0()  asm volatile("cp.async.wait_group 0;" ::: "memory")

#define LDMATRIX_X4(r0, r1, r2, r3, addr)                                    \
    asm volatile("ldmatrix.sync.aligned.m8n8.x4.shared.b16 {%0,%1,%2,%3}, [%4];" \
                 : "=r"(r0), "=r"(r1), "=r"(r2), "=r"(r3) : "r"(addr))

__device__ __forceinline__ void mma_f16(float& d0, float& d1, float& d2, float& d3,
                                        uint32_t a0, uint32_t a1, uint32_t a2, uint32_t a3,
                                        uint32_t b0, uint32_t b1) {
    asm volatile(
        "mma.sync.aligned.m16n8k16.row.col.f32.f16.f16.f32 "
        "{%0,%1,%2,%3}, {%4,%5,%6,%7}, {%8,%9}, {%0,%1,%2,%3};"
        : "+f"(d0), "+f"(d1), "+f"(d2), "+f"(d3)
        : "r"(a0), "r"(a1), "r"(a2), "r"(a3), "r"(b0), "r"(b1));
}

// ============================================================================
// K2a: y = x@W^T (unscaled) fp32 + fp16-transposed. Runs FIRST (no deps).
// ============================================================================
__global__ void __launch_bounds__(128) k2a_y(const float* __restrict__ x,
                                             const float* __restrict__ W) {
    extern __shared__ float sh2[];
    float* Ws = sh2;                 // [128][132]
    float* xs = sh2 + 128 * 132;     // [16][128]
    const int c = threadIdx.x;
    const int j0 = blockIdx.x * 16;

    for (int idx = c; idx < 128 * 128; idx += 128)
        Ws[(idx >> 7) * 132 + (idx & 127)] = W[idx];
    for (int idx = c; idx < 16 * 128; idx += 128)
        xs[idx] = x[(size_t)(j0 + (idx >> 7)) * 128 + (idx & 127)];
    __syncthreads();

    float acc[16];
    #pragma unroll
    for (int r = 0; r < 16; r++) acc[r] = 0.0f;
    for (int k = 0; k < 128; k += 4) {
        float4 wv = *reinterpret_cast<const float4*>(&Ws[c * 132 + k]);
        #pragma unroll
        for (int r = 0; r < 16; r++) {
            float4 xv = *reinterpret_cast<const float4*>(&xs[r * 128 + k]);
            acc[r] += xv.x * wv.x + xv.y * wv.y + xv.z * wv.z + xv.w * wv.w;
        }
    }
    #pragma unroll
    for (int r = 0; r < 16; r++)
        g_y[(size_t)(j0 + r) * 128 + c] = acc[r];
    #pragma unroll
    for (int m = 0; m < 2; m++) {
        uint4 q;
        q.x = pack_f16x2(acc[8*m+0], acc[8*m+1]);
        q.y = pack_f16x2(acc[8*m+2], acc[8*m+3]);
        q.z = pack_f16x2(acc[8*m+4], acc[8*m+5]);
        q.w = pack_f16x2(acc[8*m+6], acc[8*m+7]);
        *reinterpret_cast<uint4*>(&g_yT_h[(size_t)c * NROWS + j0 + 8 * m]) = q;
    }
}

// ============================================================================
// K1: dinv[i] = rsqrt(1 + sum_j adj[i][j])   grid 8192 (full DRAM bandwidth)
// ============================================================================
__global__ void __launch_bounds__(256) k1_rowsum(const float* __restrict__ adj) {
    const int row = blockIdx.x;
    const float4* p = reinterpret_cast<const float4*>(adj + (size_t)row * NROWS);
    float s = 0.0f;
    #pragma unroll 4
    for (int i = threadIdx.x; i < NROWS / 4; i += 256) {
        float4 v = p[i];
        s += (v.x + v.y) + (v.z + v.w);
    }
    #pragma unroll
    for (int o = 16; o > 0; o >>= 1) s += __shfl_xor_sync(0xFFFFFFFFu, s, o);
    __shared__ float ws[8];
    if ((threadIdx.x & 31) == 0) ws[threadIdx.x >> 5] = s;
    __syncthreads();
    if (threadIdx.x == 0) {
        float t = 0.0f;
        #pragma unroll
        for (int i = 0; i < 8; i++) t += ws[i];
        g_dinv[row] = rsqrtf(t + 1.0f);
    }
}

// ============================================================================
// K3: 256 CTAs (64 tiles x 4 ksplits). R4-placement GEMM, dinv folded into
// the A fp32->fp16 conversion, last-arriver fused epilogue (replaces K4).
// ============================================================================
static constexpr int BK = 32;
static constexpr int RSTRIDE = 80;
static constexpr int TILE_B = 128 * RSTRIDE;
static constexpr int SMEM_K3 = 4 * TILE_B;         // 40960

__global__ void __launch_bounds__(256, 2) k3_gemm(const float* __restrict__ adj,
                                                  const float* __restrict__ bias,
                                                  float* __restrict__ out) {
    extern __shared__ char sm3[];
    const uint32_t base = smem_u32(sm3);
    const int tid = threadIdx.x;
    const int wid = tid >> 5, lane = tid & 31;
    const int gid = lane >> 2, tig = lane & 3;
    const int wm = wid & 3;
    const int wn = wid >> 2;

    const int tile = blockIdx.x & 63;
    const int ks = blockIdx.x >> 6;
    const int m0 = tile * 128;
    const int kbase = ks * 2048;
    const int NK = 2048 / BK;        // 64

    const uint32_t Ab0 = base, Ab1 = base + TILE_B;
    const uint32_t Bb0 = base + 2 * TILE_B, Bb1 = base + 3 * TILE_B;

    const int ar[4] = { (tid + 0) >> 3, (tid + 256) >> 3, (tid + 512) >> 3, (tid + 768) >> 3 };
    const int aqf = tid & 7;

    float4 pf[4];
    float4 dv;
    #define LDA(kt) do {                                                         \
        const int _k0 = kbase + (kt) * BK;                                       \
        dv = *reinterpret_cast<const float4*>(g_dinv + _k0 + aqf * 4);           \
        _Pragma("unroll")                                                        \
        for (int i = 0; i < 4; i++)                                              \
            pf[i] = *reinterpret_cast<const float4*>(                            \
                adj + (size_t)(m0 + ar[i]) * NROWS + _k0 + aqf * 4);             \
    } while (0)

    #define STA(buf) do {                                                        \
        _Pragma("unroll")                                                        \
        for (int i = 0; i < 4; i++) {                                            \
            uint32_t h0 = pack_f16x2(pf[i].x * dv.x, pf[i].y * dv.y);            \
            uint32_t h1 = pack_f16x2(pf[i].z * dv.z, pf[i].w * dv.w);            \
            asm volatile("st.shared.v2.b32 [%0], {%1,%2};"                       \
                :: "r"((buf) + ar[i] * RSTRIDE + aqf * 8), "r"(h0), "r"(h1)      \
                : "memory");                                                     \
        }                                                                        \
    } while (0)

    #define CPB(kt, buf) do {                                                    \
        const int _k0 = kbase + (kt) * BK;                                       \
        _Pragma("unroll")                                                        \
        for (int i = 0; i < 2; i++) {                                            \
            const int id = tid + 256 * i;                                        \
            const int r = id >> 2, q = id & 3;                                   \
            CP_ASYNC16((buf) + r * RSTRIDE + q * 16,                             \
                       (const void*)(g_yT_h + (size_t)r * NROWS + _k0 + q * 8)); \
        }                                                                        \
    } while (0)

    float acc[2][8][4];
    #pragma unroll
    for (int i = 0; i < 2; i++)
        #pragma unroll
        for (int j = 0; j < 8; j++)
            #pragma unroll
            for (int t = 0; t < 4; t++) acc[i][j][t] = 0.0f;

    LDA(0);
    CPB(0, Bb0); CP_COMMIT();

    for (int kt = 0; kt < NK; kt++) {
        const uint32_t Ab = (kt & 1) ? Ab1 : Ab0;
        const uint32_t Bb = (kt & 1) ? Bb1 : Bb0;
        STA(Ab);
        CP_WAIT0();
        __syncthreads();
        if (kt + 1 < NK) {
            LDA(kt + 1);
            CPB(kt + 1, (kt & 1) ? Bb0 : Bb1);
            CP_COMMIT();
        }
        #pragma unroll
        for (int s = 0; s < 2; s++) {
            const int ch = 2 * s + (lane >> 4);
            uint32_t a[2][4], b[4][4];
            #pragma unroll
            for (int mt = 0; mt < 2; mt++) {
                const int r = wm * 32 + mt * 16 + (lane & 15);
                LDMATRIX_X4(a[mt][0], a[mt][1], a[mt][2], a[mt][3],
                            Ab + r * RSTRIDE + ch * 16);
            }
            #pragma unroll
            for (int p = 0; p < 4; p++) {
                const int r = wn * 64 + p * 16 + (lane & 15);
                LDMATRIX_X4(b[p][0], b[p][1], b[p][2], b[p][3],
                            Bb + r * RSTRIDE + ch * 16);
            }
            #pragma unroll
            for (int mt = 0; mt < 2; mt++)
                #pragma unroll
                for (int nt = 0; nt < 8; nt++) {
                    const int p = nt >> 1, sel = nt & 1;
                    mma_f16(acc[mt][nt][0], acc[mt][nt][1], acc[mt][nt][2], acc[mt][nt][3],
                            a[mt][0], a[mt][1], a[mt][2], a[mt][3],
                            b[p][sel], b[p][2 + sel]);
                }
        }
        __syncthreads();
    }

    // ---- write this slice's partial ----
    float* part = g_part + (size_t)ks * (NROWS * CDIM) + (size_t)m0 * CDIM;
    #pragma unroll
    for (int mt = 0; mt < 2; mt++) {
        const int r0 = wm * 32 + mt * 16 + gid;
        #pragma unroll
        for (int nt = 0; nt < 8; nt++) {
            const int col = wn * 64 + nt * 8 + tig * 2;
            *reinterpret_cast<float2*>(part + (size_t)r0 * 128 + col) =
                make_float2(acc[mt][nt][0], acc[mt][nt][1]);
            *reinterpret_cast<float2*>(part + (size_t)(r0 + 8) * 128 + col) =
                make_float2(acc[mt][nt][2], acc[mt][nt][3]);
        }
    }
    #undef LDA
    #undef STA
    #undef CPB

    // ---- last-arriver fused epilogue (non-blocking, deterministic) ----
    __threadfence();
    __syncthreads();
    __shared__ int s_last;
    if (tid == 0) {
        const int old = atomicAdd(&g_cnt[tile], 1);
        s_last = (old == 3);
        if (old == 3) g_cnt[tile] = 0;   // self-reset for next graph replay
    }
    __syncthreads();
    if (s_last) {
        __threadfence();
        const size_t tbase = (size_t)m0 * CDIM;
        for (int e = tid; e < 128 * CDIM / 4; e += 256) {
            const int r = e >> 5;
            const int c4 = (e & 31) * 4;
            const size_t off = tbase + (size_t)r * CDIM + c4;
            float4 sum = *reinterpret_cast<const float4*>(g_part + off);
            #pragma unroll
            for (int sp = 1; sp < 4; sp++) {
                const float4 p = *reinterpret_cast<const float4*>(
                    g_part + (size_t)sp * (NROWS * CDIM) + off);
                sum.x += p.x; sum.y += p.y; sum.z += p.z; sum.w += p.w;
            }
            const float di = g_dinv[m0 + r];
            const float d2 = di * di;
            const float4 y4 = *reinterpret_cast<const float4*>(g_y + off);
            const float4 bb = *reinterpret_cast<const float4*>(bias + c4);
            float4 o;
            o.x = di * sum.x + d2 * y4.x + bb.x;
            o.y = di * sum.y + d2 * y4.y + bb.y;
            o.z = di * sum.z + d2 * y4.z + bb.z;
            o.w = di * sum.w + d2 * y4.w + bb.w;
            *reinterpret_cast<float4*>(out + off) = o;
        }
    }
}

// ============================================================================
// launch: strictly sequential on stream 0 — no forks, no events, no hazards
// ============================================================================
extern "C" void kernel_launch(void* const* d_in, const int* in_sizes, int n_in,
                              void* d_out, int out_size) {
    (void)in_sizes; (void)n_in; (void)out_size;
    const float* x   = (const float*)d_in[0];
    const float* adj = (const float*)d_in[1];
    const float* W   = (const float*)d_in[2];
    const float* b   = (const float*)d_in[3];
    float* out = (float*)d_out;

    const int smem_k2 = (128 * 132 + 16 * 128) * 4;
    cudaFuncSetAttribute(k2a_y, cudaFuncAttributeMaxDynamicSharedMemorySize, smem_k2);
    cudaFuncSetAttribute(k3_gemm, cudaFuncAttributeMaxDynamicSharedMemorySize, SMEM_K3);

    k2a_y<<<NROWS / 16, 128, smem_k2>>>(x, W);
    k1_rowsum<<<NROWS, 256>>>(adj);
    k3_gemm<<<256, 256, SMEM_K3>>>(adj, b, out);
}

// round 17
// speedup vs baseline: 1.4129x; 1.3825x over previous
#include <cuda_runtime.h>
#include <cuda_fp16.h>
#include <cstdint>
#include <cstddef>

#define NROWS 8192
#define CDIM  128

// ---------------- device scratch ----------------
__device__ float  g_dinv[NROWS];
__device__ __half g_zT_h[CDIM * NROWS];          // zT[c][j] = dinv_j*(xW^T)_{j,c} fp16
__device__ float  g_z[NROWS * CDIM];             // z[j][c] fp32 (dinv-scaled)
__device__ float  g_part[4 * NROWS * CDIM];      // split-K partials

// ---------------- helpers ----------------
__device__ __forceinline__ uint32_t smem_u32(const void* p) {
    uint32_t a;
    asm("{ .reg .u64 t; cvta.to.shared.u64 t, %1; cvt.u32.u64 %0, t; }" : "=r"(a) : "l"(p));
    return a;
}
__device__ __forceinline__ uint32_t pack_f16x2(float x, float y) {
    uint32_t h;
    asm("cvt.rn.f16x2.f32 %0, %1, %2;" : "=r"(h) : "f"(y), "f"(x));
    return h;
}
#define CP_ASYNC16(dst, src) \
    asm volatile("cp.async.cg.shared.global [%0], [%1], 16;" :: "r"(dst), "l"(src) : "memory")
#define CP_COMMIT() asm volatile("cp.async.commit_group;" ::: "memory")
#define CP_WAIT0()  asm volatile("cp.async.wait_group 0;" ::: "memory")

#define LDMATRIX_X4(r0, r1, r2, r3, addr)                                    \
    asm volatile("ldmatrix.sync.aligned.m8n8.x4.shared.b16 {%0,%1,%2,%3}, [%4];" \
                 : "=r"(r0), "=r"(r1), "=r"(r2), "=r"(r3) : "r"(addr))

__device__ __forceinline__ void mma_f16(float& d0, float& d1, float& d2, float& d3,
                                        uint32_t a0, uint32_t a1, uint32_t a2, uint32_t a3,
                                        uint32_t b0, uint32_t b1) {
    asm volatile(
        "mma.sync.aligned.m16n8k16.row.col.f32.f16.f16.f32 "
        "{%0,%1,%2,%3}, {%4,%5,%6,%7}, {%8,%9}, {%0,%1,%2,%3};"
        : "+f"(d0), "+f"(d1), "+f"(d2), "+f"(d3)
        : "r"(a0), "r"(a1), "r"(a2), "r"(a3), "r"(b0), "r"(b1));
}

// ============================================================================
// K1: dinv[i] = rsqrt(1 + sum_j adj[i][j])   grid 8192
// ============================================================================
__global__ void __launch_bounds__(256) k1_rowsum(const float* __restrict__ adj) {
    const int row = blockIdx.x;
    const float4* p = reinterpret_cast<const float4*>(adj + (size_t)row * NROWS);
    float s = 0.0f;
    #pragma unroll 4
    for (int i = threadIdx.x; i < NROWS / 4; i += 256) {
        float4 v = p[i];
        s += (v.x + v.y) + (v.z + v.w);
    }
    #pragma unroll
    for (int o = 16; o > 0; o >>= 1) s += __shfl_xor_sync(0xFFFFFFFFu, s, o);
    __shared__ float ws[8];
    if ((threadIdx.x & 31) == 0) ws[threadIdx.x >> 5] = s;
    __syncthreads();
    if (threadIdx.x == 0) {
        float t = 0.0f;
        #pragma unroll
        for (int i = 0; i < 8; i++) t += ws[i];
        g_dinv[row] = rsqrtf(t + 1.0f);
    }
}

// ============================================================================
// K2m: z = dinv .* (x @ W^T) via fp16 mma. 64 CTAs, tile 128x128, K=128.
// A = x (fp32->fp16), B = W (fp32->fp16, K-major rows = channels).
// Outputs g_z (fp32) and g_zT_h (fp16, via smem transpose staging).
// ============================================================================
static constexpr int RSTRIDE = 80;
static constexpr int TILE_B = 128 * RSTRIDE;          // 10240 per 128x32 chunk
static constexpr int SMEM_K2M = 8 * TILE_B;           // A[4] + B[4] = 81920
static constexpr int TSTRIDE = 288;                   // transpose staging row bytes

__global__ void __launch_bounds__(256) k2m(const float* __restrict__ x,
                                           const float* __restrict__ W) {
    extern __shared__ char smem[];
    const uint32_t base = smem_u32(smem);
    const int tid = threadIdx.x;
    const int wid = tid >> 5, lane = tid & 31;
    const int gid = lane >> 2, tig = lane & 3;
    const int wm = wid & 3;
    const int wn = wid >> 2;
    const int j0 = blockIdx.x * 128;

    // ---- load x tile and W, convert to fp16, store in 4 BK=32 chunks each ----
    #pragma unroll
    for (int i = 0; i < 16; i++) {
        const int id = tid + 256 * i;          // 0..4095
        const int r = id >> 5;                 // row / channel 0..127
        const int c4 = id & 31;                // float4 index within 128 floats
        const int kt = c4 >> 3, qf = c4 & 7;
        const uint32_t dst = (uint32_t)(kt * TILE_B + r * RSTRIDE + qf * 8);
        float4 v = *reinterpret_cast<const float4*>(x + (size_t)(j0 + r) * 128 + c4 * 4);
        uint32_t h0 = pack_f16x2(v.x, v.y);
        uint32_t h1 = pack_f16x2(v.z, v.w);
        asm volatile("st.shared.v2.b32 [%0], {%1,%2};"
                     :: "r"(base + dst), "r"(h0), "r"(h1) : "memory");
        float4 w = *reinterpret_cast<const float4*>(W + (size_t)r * 128 + c4 * 4);
        uint32_t g0 = pack_f16x2(w.x, w.y);
        uint32_t g1 = pack_f16x2(w.z, w.w);
        asm volatile("st.shared.v2.b32 [%0], {%1,%2};"
                     :: "r"(base + 4 * TILE_B + dst), "r"(g0), "r"(g1) : "memory");
    }
    __syncthreads();

    // ---- mma mainloop (same structure as k3's inner loop) ----
    float acc[2][8][4];
    #pragma unroll
    for (int i = 0; i < 2; i++)
        #pragma unroll
        for (int j = 0; j < 8; j++)
            #pragma unroll
            for (int t = 0; t < 4; t++) acc[i][j][t] = 0.0f;

    #pragma unroll
    for (int kt = 0; kt < 4; kt++) {
        const uint32_t Ab = base + kt * TILE_B;
        const uint32_t Bb = base + (4 + kt) * TILE_B;
        #pragma unroll
        for (int s = 0; s < 2; s++) {
            const int ch = 2 * s + (lane >> 4);
            uint32_t a[2][4], b[4][4];
            #pragma unroll
            for (int mt = 0; mt < 2; mt++) {
                const int r = wm * 32 + mt * 16 + (lane & 15);
                LDMATRIX_X4(a[mt][0], a[mt][1], a[mt][2], a[mt][3],
                            Ab + r * RSTRIDE + ch * 16);
            }
            #pragma unroll
            for (int p = 0; p < 4; p++) {
                const int r = wn * 64 + p * 16 + (lane & 15);
                LDMATRIX_X4(b[p][0], b[p][1], b[p][2], b[p][3],
                            Bb + r * RSTRIDE + ch * 16);
            }
            #pragma unroll
            for (int mt = 0; mt < 2; mt++)
                #pragma unroll
                for (int nt = 0; nt < 8; nt++) {
                    const int p = nt >> 1, sel = nt & 1;
                    mma_f16(acc[mt][nt][0], acc[mt][nt][1], acc[mt][nt][2], acc[mt][nt][3],
                            a[mt][0], a[mt][1], a[mt][2], a[mt][3],
                            b[p][sel], b[p][2 + sel]);
                }
        }
    }
    __syncthreads();   // done reading A/B smem; reuse for transpose staging

    // ---- scale by dinv, write g_z, stage fp16 transpose in smem ----
    __half* st16 = reinterpret_cast<__half*>(smem);     // [c][r] stride TSTRIDE/2 halfs
    #pragma unroll
    for (int mt = 0; mt < 2; mt++) {
        const int r0 = wm * 32 + mt * 16 + gid;
        const int r1 = r0 + 8;
        const float di0 = g_dinv[j0 + r0];
        const float di1 = g_dinv[j0 + r1];
        #pragma unroll
        for (int nt = 0; nt < 8; nt++) {
            const int col = wn * 64 + nt * 8 + tig * 2;
            const float v00 = di0 * acc[mt][nt][0];
            const float v01 = di0 * acc[mt][nt][1];
            const float v10 = di1 * acc[mt][nt][2];
            const float v11 = di1 * acc[mt][nt][3];
            *reinterpret_cast<float2*>(g_z + (size_t)(j0 + r0) * 128 + col) =
                make_float2(v00, v01);
            *reinterpret_cast<float2*>(g_z + (size_t)(j0 + r1) * 128 + col) =
                make_float2(v10, v11);
            st16[(size_t)col * (TSTRIDE / 2) + r0]       = __float2half_rn(v00);
            st16[(size_t)(col + 1) * (TSTRIDE / 2) + r0] = __float2half_rn(v01);
            st16[(size_t)col * (TSTRIDE / 2) + r1]       = __float2half_rn(v10);
            st16[(size_t)(col + 1) * (TSTRIDE / 2) + r1] = __float2half_rn(v11);
        }
    }
    __syncthreads();

    // ---- vectorized transpose write: zT_h[c][j0..j0+127] ----
    #pragma unroll
    for (int i = 0; i < 8; i++) {
        const int id = tid + 256 * i;          // 0..2047
        const int c = id >> 4;
        const int seg = id & 15;               // 8 halfs per segment
        const uint4 q = *reinterpret_cast<const uint4*>(smem + (size_t)c * TSTRIDE + seg * 16);
        *reinterpret_cast<uint4*>(g_zT_h + (size_t)c * NROWS + j0 + seg * 8) = q;
    }
}

// ============================================================================
// K3: split-K fp16 GEMM — byte-identical to the 174.4us champion (R4).
// ============================================================================
static constexpr int BK = 32;
static constexpr int SMEM_K3 = 4 * TILE_B;         // 40960

__global__ void __launch_bounds__(256, 2) k3_gemm(const float* __restrict__ adj) {
    extern __shared__ char sm3[];
    const uint32_t base = smem_u32(sm3);
    const int tid = threadIdx.x;
    const int wid = tid >> 5, lane = tid & 31;
    const int gid = lane >> 2, tig = lane & 3;
    const int wm = wid & 3;
    const int wn = wid >> 2;

    const int tile = blockIdx.x & 63;
    const int ks = blockIdx.x >> 6;
    const int m0 = tile * 128;
    const int kbase = ks * 2048;
    const int NK = 2048 / BK;        // 64

    const uint32_t Ab0 = base, Ab1 = base + TILE_B;
    const uint32_t Bb0 = base + 2 * TILE_B, Bb1 = base + 3 * TILE_B;

    const int ar[4] = { (tid + 0) >> 3, (tid + 256) >> 3, (tid + 512) >> 3, (tid + 768) >> 3 };
    const int aqf = tid & 7;

    float4 pf[4];
    #define LDA(kt) do {                                                         \
        const int _k0 = kbase + (kt) * BK;                                       \
        _Pragma("unroll")                                                        \
        for (int i = 0; i < 4; i++)                                              \
            pf[i] = *reinterpret_cast<const float4*>(                            \
                adj + (size_t)(m0 + ar[i]) * NROWS + _k0 + aqf * 4);             \
    } while (0)

    #define STA(buf) do {                                                        \
        _Pragma("unroll")                                                        \
        for (int i = 0; i < 4; i++) {                                            \
            uint32_t h0 = pack_f16x2(pf[i].x, pf[i].y);                          \
            uint32_t h1 = pack_f16x2(pf[i].z, pf[i].w);                          \
            asm volatile("st.shared.v2.b32 [%0], {%1,%2};"                       \
                :: "r"((buf) + ar[i] * RSTRIDE + aqf * 8), "r"(h0), "r"(h1)      \
                : "memory");                                                     \
        }                                                                        \
    } while (0)

    #define CPB(kt, buf) do {                                                    \
        const int _k0 = kbase + (kt) * BK;                                       \
        _Pragma("unroll")                                                        \
        for (int i = 0; i < 2; i++) {                                            \
            const int id = tid + 256 * i;                                        \
            const int r = id >> 2, q = id & 3;                                   \
            CP_ASYNC16((buf) + r * RSTRIDE + q * 16,                             \
                       (const void*)(g_zT_h + (size_t)r * NROWS + _k0 + q * 8)); \
        }                                                                        \
    } while (0)

    float acc[2][8][4];
    #pragma unroll
    for (int i = 0; i < 2; i++)
        #pragma unroll
        for (int j = 0; j < 8; j++)
            #pragma unroll
            for (int t = 0; t < 4; t++) acc[i][j][t] = 0.0f;

    LDA(0);
    CPB(0, Bb0); CP_COMMIT();

    for (int kt = 0; kt < NK; kt++) {
        const uint32_t Ab = (kt & 1) ? Ab1 : Ab0;
        const uint32_t Bb = (kt & 1) ? Bb1 : Bb0;
        STA(Ab);
        CP_WAIT0();
        __syncthreads();
        if (kt + 1 < NK) {
            LDA(kt + 1);
            CPB(kt + 1, (kt & 1) ? Bb0 : Bb1);
            CP_COMMIT();
        }
        #pragma unroll
        for (int s = 0; s < 2; s++) {
            const int ch = 2 * s + (lane >> 4);
            uint32_t a[2][4], b[4][4];
            #pragma unroll
            for (int mt = 0; mt < 2; mt++) {
                const int r = wm * 32 + mt * 16 + (lane & 15);
                LDMATRIX_X4(a[mt][0], a[mt][1], a[mt][2], a[mt][3],
                            Ab + r * RSTRIDE + ch * 16);
            }
            #pragma unroll
            for (int p = 0; p < 4; p++) {
                const int r = wn * 64 + p * 16 + (lane & 15);
                LDMATRIX_X4(b[p][0], b[p][1], b[p][2], b[p][3],
                            Bb + r * RSTRIDE + ch * 16);
            }
            #pragma unroll
            for (int mt = 0; mt < 2; mt++)
                #pragma unroll
                for (int nt = 0; nt < 8; nt++) {
                    const int p = nt >> 1, sel = nt & 1;
                    mma_f16(acc[mt][nt][0], acc[mt][nt][1], acc[mt][nt][2], acc[mt][nt][3],
                            a[mt][0], a[mt][1], a[mt][2], a[mt][3],
                            b[p][sel], b[p][2 + sel]);
                }
        }
        __syncthreads();
    }

    float* part = g_part + (size_t)ks * (NROWS * CDIM) + (size_t)m0 * CDIM;
    #pragma unroll
    for (int mt = 0; mt < 2; mt++) {
        const int r0 = wm * 32 + mt * 16 + gid;
        #pragma unroll
        for (int nt = 0; nt < 8; nt++) {
            const int col = wn * 64 + nt * 8 + tig * 2;
            *reinterpret_cast<float2*>(part + (size_t)r0 * 128 + col) =
                make_float2(acc[mt][nt][0], acc[mt][nt][1]);
            *reinterpret_cast<float2*>(part + (size_t)(r0 + 8) * 128 + col) =
                make_float2(acc[mt][nt][2], acc[mt][nt][3]);
        }
    }
    #undef LDA
    #undef STA
    #undef CPB
}

// ============================================================================
// K4: out[i][c] = dinv_i * (sum_s part[s][i][c] + z[i][c]) + b[c]
// ============================================================================
__global__ void __launch_bounds__(256) k4_reduce(const float* __restrict__ bias,
                                                 float* __restrict__ out) {
    const int idx = blockIdx.x * 256 + threadIdx.x;
    const int i = idx >> 5;
    const int c4 = (idx & 31) * 4;
    const size_t off = (size_t)i * 128 + c4;

    float4 s = *reinterpret_cast<const float4*>(g_z + off);
    #pragma unroll
    for (int sp = 0; sp < 4; sp++) {
        float4 p = *reinterpret_cast<const float4*>(g_part + (size_t)sp * (NROWS * CDIM) + off);
        s.x += p.x; s.y += p.y; s.z += p.z; s.w += p.w;
    }
    const float di = g_dinv[i];
    const float4 bb = *reinterpret_cast<const float4*>(bias + c4);
    float4 o;
    o.x = di * s.x + bb.x;
    o.y = di * s.y + bb.y;
    o.z = di * s.z + bb.z;
    o.w = di * s.w + bb.w;
    *reinterpret_cast<float4*>(out + off) = o;
}

// ============================================================================
// launch: strictly sequential on stream 0
// ============================================================================
extern "C" void kernel_launch(void* const* d_in, const int* in_sizes, int n_in,
                              void* d_out, int out_size) {
    (void)in_sizes; (void)n_in; (void)out_size;
    const float* x   = (const float*)d_in[0];
    const float* adj = (const float*)d_in[1];
    const float* W   = (const float*)d_in[2];
    const float* b   = (const float*)d_in[3];
    float* out = (float*)d_out;

    cudaFuncSetAttribute(k2m, cudaFuncAttributeMaxDynamicSharedMemorySize, SMEM_K2M);
    cudaFuncSetAttribute(k3_gemm, cudaFuncAttributeMaxDynamicSharedMemorySize, SMEM_K3);

    k1_rowsum<<<NROWS, 256>>>(adj);
    k2m<<<NROWS / 128, 256, SMEM_K2M>>>(x, W);
    k3_gemm<<<256, 256, SMEM_K3>>>(adj);
    k4_reduce<<<NROWS * CDIM / 4 / 256, 256>>>(b, out);
}